// round 4
// baseline (speedup 1.0000x reference)
#include <cuda_runtime.h>
#include <cuda_bf16.h>

// Winograd F(4x4,3x3), filter already in 6x6 transform domain.
// N=16, Cin=Cout=64, H=W=128, pad=1, nt=32.
//
// CTA = (cout-half ch: 32 couts, tile-row tp, image n), grid (2,32,16), 256 thr.
// Thread tile: 16 couts x 9 points x 1 tile (lane = tile). acc[16][9].
// Per cin: stage D[6][130] + Wt[36 pts][32 couts] (prefetched, precomputed idx),
//          U = BT@D, V per tile -> sV[36][32], GEMM with broadcast W LDS.128.
// Epilogue: 8 chunks of 4 couts via sM, A-transform + bias, float4 stores.

#define HH 128

__global__ __launch_bounds__(256, 1)
void winograd_v3_kernel(const float* __restrict__ x,
                        const float* __restrict__ w,
                        const float* __restrict__ bias,
                        float* __restrict__ y)
{
    __shared__ float sD[6][132];
    __shared__ float sU[6][132];
    __shared__ float sV[36][32];
    __shared__ float sWt[36 * 36];   // [point][cout], 36-stride (16B aligned rows)
    __shared__ float sM[4][36][32];

    const int tid = threadIdx.x;
    const int ch  = blockIdx.x;   // 0..1 : couts ch*32 .. ch*32+31
    const int tp  = blockIdx.y;   // 0..31
    const int n   = blockIdx.z;   // 0..15

    const int t  = tid & 31;      // lane = tile
    const int wp = tid >> 5;      // warp 0..7
    const int cg = wp & 1;        // cout group of 16
    const int pg = wp >> 1;       // point group of 9

    const int r0 = tp * 4 - 1;

    float acc[16][9];
#pragma unroll
    for (int i = 0; i < 16; i++)
#pragma unroll
        for (int j = 0; j < 9; j++) acc[i][j] = 0.f;

    // ---- precompute staging indices (invariant over cin) ----
    int  dGoff[4];  float* dDst[4];  bool dSt[4], dLd[4];
#pragma unroll
    for (int k = 0; k < 4; k++) {
        int l = tid + 256 * k;
        bool vl = (l < 780);
        int li = vl ? l : 0;
        int i = li / 130;
        int j = li - i * 130;
        int r = r0 + i, c = j - 1;
        dSt[k]   = vl;
        dLd[k]   = vl && ((unsigned)r < HH) && ((unsigned)c < HH);
        dGoff[k] = r * HH + c;
        dDst[k]  = &sD[i][j];
    }
    int  wGoff[5];  float* wDst[5];  bool wV[5];
#pragma unroll
    for (int k = 0; k < 5; k++) {
        int l = tid + 256 * k;
        bool vl = (l < 1152);
        int li = vl ? l : 0;
        int co = li / 36;
        int p  = li - co * 36;
        wV[k]    = vl;
        wGoff[k] = co * (64 * 36) + p;     // per-cin add 36
        wDst[k]  = &sWt[p * 36 + co];
    }

    const float* xcur = x + (size_t)n * 64 * HH * HH;     // += 16384 per cin
    const float* wcur = w + (size_t)(ch * 32) * (64 * 36); // += 36 per cin

    // ---- prefetch cin 0 ----
    float dreg[4], wreg[5];
#pragma unroll
    for (int k = 0; k < 4; k++) dreg[k] = dLd[k] ? __ldg(xcur + dGoff[k]) : 0.f;
#pragma unroll
    for (int k = 0; k < 5; k++) wreg[k] = wV[k] ? __ldg(wcur + wGoff[k]) : 0.f;

    for (int cin = 0; cin < 64; ++cin) {
        __syncthreads();   // prev GEMM done

        // ---- store staged data ----
#pragma unroll
        for (int k = 0; k < 4; k++) if (dSt[k]) *dDst[k] = dreg[k];
#pragma unroll
        for (int k = 0; k < 5; k++) if (wV[k]) *wDst[k] = wreg[k];

        // ---- prefetch next cin ----
        if (cin + 1 < 64) {
            const float* xp = xcur + 16384;
            const float* wq = wcur + 36 + 36;  // next cin
            // note: wcur already advanced below; use explicit bases:
        }
        xcur += 16384;
        wcur += 36;
        if (cin + 1 < 64) {
#pragma unroll
            for (int k = 0; k < 4; k++) dreg[k] = dLd[k] ? __ldg(xcur + dGoff[k]) : 0.f;
#pragma unroll
            for (int k = 0; k < 5; k++) wreg[k] = wV[k] ? __ldg(wcur + wGoff[k]) : 0.f;
        }

        __syncthreads();

        // ---- U = BT @ D (130 columns) ----
        if (tid < 130) {
            float d0 = sD[0][tid], d1 = sD[1][tid], d2 = sD[2][tid];
            float d3 = sD[3][tid], d4 = sD[4][tid], d5 = sD[5][tid];
            sU[0][tid] =  4.f * d0 - 5.f * d2 + d4;
            sU[1][tid] = -4.f * d1 - 4.f * d2 + d3 + d4;
            sU[2][tid] =  4.f * d1 - 4.f * d2 - d3 + d4;
            sU[3][tid] = -2.f * d1 -       d2 + 2.f * d3 + d4;
            sU[4][tid] =  2.f * d1 -       d2 - 2.f * d3 + d4;
            sU[5][tid] =  4.f * d1 - 5.f * d3 + d5;
        }

        __syncthreads();

        // ---- V: warp a handles row a, lane = tile ----
        if (tid < 192) {
            int a  = tid >> 5;
            int tt = tid & 31;
            float4 u03 = *(const float4*)&sU[a][4 * tt];
            float2 u45 = *(const float2*)&sU[a][4 * tt + 4];
            float u0 = u03.x, u1 = u03.y, u2 = u03.z, u3 = u03.w;
            float u4 = u45.x, u5 = u45.y;
            sV[a * 6 + 0][tt] =  4.f * u0 - 5.f * u2 + u4;
            sV[a * 6 + 1][tt] = -4.f * u1 - 4.f * u2 + u3 + u4;
            sV[a * 6 + 2][tt] =  4.f * u1 - 4.f * u2 - u3 + u4;
            sV[a * 6 + 3][tt] = -2.f * u1 -       u2 + 2.f * u3 + u4;
            sV[a * 6 + 4][tt] =  2.f * u1 -       u2 - 2.f * u3 + u4;
            sV[a * 6 + 5][tt] =  4.f * u1 - 5.f * u3 + u5;
        }

        __syncthreads();

        // ---- GEMM: acc[co][k] += Wt[pg*9+k][cg*16+co] * V[pg*9+k][t] ----
        {
            float v[9];
            const float* vb = &sV[pg * 9][0] + t;
#pragma unroll
            for (int k = 0; k < 9; k++) v[k] = vb[k * 32];

            const float* wtb = &sWt[(pg * 9) * 36 + cg * 16];
#pragma unroll
            for (int k = 0; k < 9; k++) {
                const float4* wr = (const float4*)(wtb + k * 36);
                float4 a0 = wr[0], a1 = wr[1], a2 = wr[2], a3 = wr[3];
                float vk = v[k];
                acc[ 0][k] += a0.x * vk;  acc[ 1][k] += a0.y * vk;
                acc[ 2][k] += a0.z * vk;  acc[ 3][k] += a0.w * vk;
                acc[ 4][k] += a1.x * vk;  acc[ 5][k] += a1.y * vk;
                acc[ 6][k] += a1.z * vk;  acc[ 7][k] += a1.w * vk;
                acc[ 8][k] += a2.x * vk;  acc[ 9][k] += a2.y * vk;
                acc[10][k] += a2.z * vk;  acc[11][k] += a2.w * vk;
                acc[12][k] += a3.x * vk;  acc[13][k] += a3.y * vk;
                acc[14][k] += a3.z * vk;  acc[15][k] += a3.w * vk;
            }
        }
    }

    // ================= epilogue: 8 chunks of 4 couts =================
#pragma unroll
    for (int c = 0; c < 8; c++) {
        if (cg == (c >> 2)) {
            const int base = (c & 3) * 4;
#pragma unroll
            for (int cl = 0; cl < 4; cl++) {
#pragma unroll
                for (int k = 0; k < 9; k++) {
                    sM[cl][pg * 9 + k][t] = acc[base + cl][k];
                }
            }
        }
        __syncthreads();

        if (tid < 128) {
            int cl = tid >> 5;
            int tt = tid & 31;
            int co_g = ch * 32 + c * 4 + cl;
            float bval = bias[co_g];

            float m[36];
#pragma unroll
            for (int p = 0; p < 36; p++) m[p] = sM[cl][p][tt];

            float z[24];
#pragma unroll
            for (int b = 0; b < 6; b++) {
                float m0 = m[b], m1 = m[6 + b], m2 = m[12 + b];
                float m3 = m[18 + b], m4 = m[24 + b], m5 = m[30 + b];
                z[0 * 6 + b] = m0 + m1 + m2 + m3 + m4;
                z[1 * 6 + b] = m1 - m2 + 2.f * m3 - 2.f * m4;
                z[2 * 6 + b] = m1 + m2 + 4.f * m3 + 4.f * m4;
                z[3 * 6 + b] = m1 - m2 + 8.f * m3 - 8.f * m4 + m5;
            }

            float* ybase = y + (((size_t)(n * 64 + co_g)) * HH + tp * 4) * HH + tt * 4;
#pragma unroll
            for (int xr = 0; xr < 4; xr++) {
                float T0 = z[xr * 6 + 0], T1 = z[xr * 6 + 1], T2 = z[xr * 6 + 2];
                float T3 = z[xr * 6 + 3], T4 = z[xr * 6 + 4], T5 = z[xr * 6 + 5];
                float4 o;
                o.x = T0 + T1 + T2 + T3 + T4 + bval;
                o.y = T1 - T2 + 2.f * T3 - 2.f * T4 + bval;
                o.z = T1 + T2 + 4.f * T3 + 4.f * T4 + bval;
                o.w = T1 - T2 + 8.f * T3 - 8.f * T4 + T5 + bval;
                *(float4*)(ybase + (size_t)xr * HH) = o;
            }
        }
        __syncthreads();
    }
}

extern "C" void kernel_launch(void* const* d_in, const int* in_sizes, int n_in,
                              void* d_out, int out_size) {
    const float* x    = (const float*)d_in[0];   // 16x64x128x128
    const float* wgt  = (const float*)d_in[1];   // 64x64x6x6 (transform domain)
    const float* bias = (const float*)d_in[2];   // 64
    float* y = (float*)d_out;                    // 16x64x128x128

    dim3 grid(2, 32, 16);   // (cout half, tile row, image)
    dim3 block(256);
    winograd_v3_kernel<<<grid, block>>>(x, wgt, bias, y);
}

// round 10
// speedup vs baseline: 2.1480x; 2.1480x over previous
#include <cuda_runtime.h>
#include <cuda_bf16.h>
#include <cstdint>

// ============================================================
// Winograd F(4x4,3x3), filter in 6x6 transform domain.
// 4-kernel pipeline (mma.sync bf16 hi/lo, base compute_103-legal):
//  W: weight split -> Wsc bf16 hi/lo
//  A: input transform -> Vsc bf16 hi/lo  ([p][tile][k], k<64 hi, 64..127 lo)
//  B: per (point p, 128-tile block): Msc[128][64] =
//     hiV*hiW + loV*hiW + hiV*loW  via mma.sync m16n8k16 bf16
//  C: output transform (AT M A) + bias -> y
// ============================================================

#define HH 128

// ---- scratch ----
__device__ unsigned short Vsc[(size_t)36 * 16384 * 128];  // bf16 bits
__device__ unsigned short Wsc[(size_t)36 * 64 * 128];     // bf16 bits: [p][cout][k], k<64 hi, 64..127 lo
__device__ float          Msc[(size_t)36 * 16384 * 64];   // [p][tile][cout]

__device__ __forceinline__ uint32_t smem_u32(const void* p) {
    uint32_t a;
    asm("{ .reg .u64 t; cvta.to.shared.u64 t, %1; cvt.u32.u64 %0, t; }" : "=r"(a) : "l"(p));
    return a;
}
__device__ __forceinline__ void ldsm_x4(uint32_t* r, uint32_t addr) {
    asm volatile("ldmatrix.sync.aligned.m8n8.x4.shared.b16 {%0,%1,%2,%3}, [%4];"
        : "=r"(r[0]), "=r"(r[1]), "=r"(r[2]), "=r"(r[3]) : "r"(addr));
}
__device__ __forceinline__ void mma16816(float* c, const uint32_t* a, const uint32_t* b) {
    asm volatile(
        "mma.sync.aligned.m16n8k16.row.col.f32.bf16.bf16.f32 "
        "{%0,%1,%2,%3}, {%4,%5,%6,%7}, {%8,%9}, {%0,%1,%2,%3};\n"
        : "+f"(c[0]), "+f"(c[1]), "+f"(c[2]), "+f"(c[3])
        : "r"(a[0]), "r"(a[1]), "r"(a[2]), "r"(a[3]), "r"(b[0]), "r"(b[1]));
}

// ==================== Kernel W: weight hi/lo split ====================
__global__ __launch_bounds__(256)
void winoW(const float* __restrict__ w)
{
    int p = blockIdx.x;
    int tid = threadIdx.x;
#pragma unroll
    for (int i = 0; i < 16; ++i) {
        int e = tid + (i << 8);          // 0..4095
        int co  = e >> 6;
        int cin = e & 63;
        float f = __ldg(w + ((size_t)co * 64 + cin) * 36 + p);
        __nv_bfloat16 h = __float2bfloat16(f);
        __nv_bfloat16 l = __float2bfloat16(f - __bfloat162float(h));
        size_t base = ((size_t)p * 64 + co) * 128;
        Wsc[base + cin]      = __bfloat16_as_ushort(h);
        Wsc[base + 64 + cin] = __bfloat16_as_ushort(l);
    }
}

// ==================== Kernel A: input transform + split ====================
// grid (32 tp, 16 n), 256 threads, dyn smem: sD[6*132] | sU[6*132] | sbuf[36][32][17]
__global__ __launch_bounds__(256, 2)
void winoA(const float* __restrict__ x)
{
    extern __shared__ char smem_raw[];
    float* sm_f = (float*)smem_raw;
    float* sD   = sm_f;            // 792
    float* sU   = sm_f + 792;      // 792
    float* sbuf = sm_f + 1584;     // 36*32*17 = 19584

    const int tid = threadIdx.x;
    const int tp  = blockIdx.x;
    const int n   = blockIdx.y;
    const int r0  = tp * 4 - 1;

    int dG[4], dI[4]; bool dS[4], dL[4];
#pragma unroll
    for (int k = 0; k < 4; k++) {
        int l = tid + 256 * k;
        bool vl = (l < 780);
        int li = vl ? l : 0;
        int i = li / 130, j = li - i * 130;
        int r = r0 + i, c = j - 1;
        dS[k] = vl;
        dL[k] = vl && ((unsigned)r < HH) && ((unsigned)c < HH);
        dG[k] = r * HH + c;
        dI[k] = i * 132 + j;
    }

    const float* xp = x + (size_t)n * 64 * HH * HH;

    for (int cin = 0; cin < 64; ++cin, xp += HH * HH) {
#pragma unroll
        for (int k = 0; k < 4; k++)
            if (dS[k]) sD[dI[k]] = dL[k] ? __ldg(xp + dG[k]) : 0.f;
        __syncthreads();

        if (tid < 130) {
            float d0 = sD[tid], d1 = sD[132 + tid], d2 = sD[264 + tid];
            float d3 = sD[396 + tid], d4 = sD[528 + tid], d5 = sD[660 + tid];
            sU[tid]       =  4.f * d0 - 5.f * d2 + d4;
            sU[132 + tid] = -4.f * d1 - 4.f * d2 + d3 + d4;
            sU[264 + tid] =  4.f * d1 - 4.f * d2 - d3 + d4;
            sU[396 + tid] = -2.f * d1 -       d2 + 2.f * d3 + d4;
            sU[528 + tid] =  2.f * d1 -       d2 - 2.f * d3 + d4;
            sU[660 + tid] =  4.f * d1 - 5.f * d3 + d5;
        }
        __syncthreads();

        if (tid < 192) {
            int a  = tid >> 5;
            int tt = tid & 31;
            const float* u = sU + a * 132 + 4 * tt;
            float u0 = u[0], u1 = u[1], u2 = u[2], u3 = u[3], u4 = u[4], u5 = u[5];
            int cl = cin & 15;
            float* vb = sbuf + ((a * 6) * 32 + tt) * 17 + cl;
            vb[0 * 32 * 17] =  4.f * u0 - 5.f * u2 + u4;
            vb[1 * 32 * 17] = -4.f * u1 - 4.f * u2 + u3 + u4;
            vb[2 * 32 * 17] =  4.f * u1 - 4.f * u2 - u3 + u4;
            vb[3 * 32 * 17] = -2.f * u1 -       u2 + 2.f * u3 + u4;
            vb[4 * 32 * 17] =  2.f * u1 -       u2 - 2.f * u3 + u4;
            vb[5 * 32 * 17] =  4.f * u1 - 5.f * u3 + u5;
        }

        if ((cin & 15) == 15) {
            __syncthreads();
            int cinBase = cin - 15;
#pragma unroll 4
            for (int it = 0; it < 36; ++it) {
                int c2 = tid & 7;
                int t  = tid >> 3;
                float v0 = sbuf[(it * 32 + t) * 17 + 2 * c2];
                float v1 = sbuf[(it * 32 + t) * 17 + 2 * c2 + 1];
                __nv_bfloat16 h0 = __float2bfloat16(v0);
                __nv_bfloat16 h1 = __float2bfloat16(v1);
                __nv_bfloat16 l0 = __float2bfloat16(v0 - __bfloat162float(h0));
                __nv_bfloat16 l1 = __float2bfloat16(v1 - __bfloat162float(h1));
                unsigned hp = (unsigned)__bfloat16_as_ushort(h0) | ((unsigned)__bfloat16_as_ushort(h1) << 16);
                unsigned lp = (unsigned)__bfloat16_as_ushort(l0) | ((unsigned)__bfloat16_as_ushort(l1) << 16);
                int tileg = (n << 10) + (tp << 5) + t;
                size_t base = ((size_t)it * 16384 + tileg) * 128;
                *(unsigned*)&Vsc[base + cinBase + 2 * c2]      = hp;
                *(unsigned*)&Vsc[base + 64 + cinBase + 2 * c2] = lp;
            }
        }
    }
}

// ==================== Kernel B: mma.sync GEMMs ====================
// grid (128 tile-blocks, 36 points), 256 threads (8 warps: 4 m x 2 n).
// smem: sA 128x128 bf16 (32KB) + sB 64x128 bf16 (16KB), XOR-swizzled 16B chunks.
#define SMB_A 0
#define SMB_B 32768
#define B_SMEM 49152

__global__ __launch_bounds__(256)
void winoB()
{
    extern __shared__ char smem_raw[];
    uint32_t sbase = smem_u32(smem_raw);
    const int tid  = threadIdx.x;
    const int lane = tid & 31;
    const int wid  = tid >> 5;
    const int tb   = blockIdx.x;
    const int p    = blockIdx.y;

    // ---- stage A: 128 rows x 16 chunks (16B), chunk swizzle c^(row&7) ----
    {
        const uint4* src = (const uint4*)(Vsc + ((size_t)p * 16384 + (size_t)tb * 128) * 128);
        uint4* dst = (uint4*)(smem_raw + SMB_A);
#pragma unroll
        for (int i = 0; i < 8; ++i) {
            int e = tid + (i << 8);        // 0..2047
            int row = e >> 4;
            int c   = e & 15;
            dst[row * 16 + (c ^ (row & 7))] = src[row * 16 + c];
        }
    }
    // ---- stage B: 64 rows x 16 chunks ----
    {
        const uint4* src = (const uint4*)(Wsc + (size_t)p * 64 * 128);
        uint4* dst = (uint4*)(smem_raw + SMB_B);
#pragma unroll
        for (int i = 0; i < 4; ++i) {
            int e = tid + (i << 8);        // 0..1023
            int row = e >> 4;
            int c   = e & 15;
            dst[row * 16 + (c ^ (row & 7))] = src[row * 16 + c];
        }
    }
    __syncthreads();

    // ---- warp tiling: 32 rows x 32 couts ----
    const int wm = (wid & 3) * 32;
    const int wn = (wid >> 2) * 32;

    float acc[2][4][4];
#pragma unroll
    for (int a = 0; a < 2; a++)
#pragma unroll
        for (int b = 0; b < 4; b++)
#pragma unroll
            for (int c = 0; c < 4; c++) acc[a][b][c] = 0.f;

    // per-lane ldmatrix row/chunk components
    const int arow0 = wm + (lane & 15);          // + mt*16
    const int achk  = lane >> 4;                 // + cbA
    // B (col-major operand = n-major storage, NON-trans ldmatrix):
    // lanes 0-7: n rows wn+0..7, k-chunk lo -> reg0 (b0, n 0-7)
    // lanes 8-15: same rows, k-chunk hi    -> reg1 (b1, n 0-7)
    // lanes 16-23: rows wn+8..15, k lo     -> reg2 (b0, n 8-15)
    // lanes 24-31: rows wn+8..15, k hi     -> reg3 (b1, n 8-15)
    const int brow0 = wn + (lane & 7) + ((lane >> 4) << 3);
    const int bchk  = (lane >> 3) & 1;

#pragma unroll
    for (int s = 0; s < 12; ++s) {
        const int term = s >> 2, sk = s & 3;
        const int cbA = (term == 1 ? 8 : 0) + 2 * sk;
        const int cbB = (term == 2 ? 8 : 0) + 2 * sk;

        uint32_t aF[2][4];
#pragma unroll
        for (int mt = 0; mt < 2; ++mt) {
            int row = arow0 + mt * 16;
            int chk = (cbA + achk) ^ (row & 7);
            ldsm_x4(aF[mt], sbase + SMB_A + row * 256 + (chk << 4));
        }
        uint32_t bF[2][4];
#pragma unroll
        for (int nt2 = 0; nt2 < 2; ++nt2) {
            int row = brow0 + nt2 * 16;
            int chk = (cbB + bchk) ^ (row & 7);
            ldsm_x4(bF[nt2], sbase + SMB_B + row * 256 + (chk << 4));
        }
#pragma unroll
        for (int mt = 0; mt < 2; ++mt)
#pragma unroll
            for (int nt2 = 0; nt2 < 2; ++nt2) {
                mma16816(acc[mt][nt2 * 2 + 0], aF[mt], &bF[nt2][0]);
                mma16816(acc[mt][nt2 * 2 + 1], aF[mt], &bF[nt2][2]);
            }
    }

    // ---- epilogue: write Msc[p][tile][cout] ----
    {
        const int r0 = tb * 128 + wm + (lane >> 2);
        const int c0 = wn + (lane & 3) * 2;
#pragma unroll
        for (int mt = 0; mt < 2; ++mt) {
#pragma unroll
            for (int nt = 0; nt < 4; ++nt) {
                float* d0 = Msc + ((size_t)p * 16384 + r0 + mt * 16) * 64 + c0 + nt * 8;
                *(float2*)d0              = make_float2(acc[mt][nt][0], acc[mt][nt][1]);
                *(float2*)(d0 + 8 * 64)   = make_float2(acc[mt][nt][2], acc[mt][nt][3]);
            }
        }
    }
}

// ==================== Kernel C: output transform + bias ====================
__global__ __launch_bounds__(256)
void winoC(const float* __restrict__ bias, float* __restrict__ y)
{
    int g = blockIdx.x * 256 + threadIdx.x;
    int cout = g & 63;
    int tile = g >> 6;
    int n  = tile >> 10;
    int ti = (tile >> 5) & 31;
    int tj = tile & 31;

    float m[36];
#pragma unroll
    for (int pp = 0; pp < 36; ++pp)
        m[pp] = __ldg(Msc + ((size_t)pp * 16384 + tile) * 64 + cout);

    float z[24];
#pragma unroll
    for (int b = 0; b < 6; b++) {
        float m0 = m[b], m1 = m[6 + b], m2 = m[12 + b];
        float m3 = m[18 + b], m4 = m[24 + b], m5 = m[30 + b];
        z[0 * 6 + b] = m0 + m1 + m2 + m3 + m4;
        z[1 * 6 + b] = m1 - m2 + 2.f * m3 - 2.f * m4;
        z[2 * 6 + b] = m1 + m2 + 4.f * m3 + 4.f * m4;
        z[3 * 6 + b] = m1 - m2 + 8.f * m3 - 8.f * m4 + m5;
    }

    float bval = __ldg(bias + cout);
    float* yb = y + (((size_t)(n * 64 + cout)) * HH + ti * 4) * HH + tj * 4;
#pragma unroll
    for (int xr = 0; xr < 4; xr++) {
        float T0 = z[xr * 6 + 0], T1 = z[xr * 6 + 1], T2 = z[xr * 6 + 2];
        float T3 = z[xr * 6 + 3], T4 = z[xr * 6 + 4], T5 = z[xr * 6 + 5];
        float4 o;
        o.x = T0 + T1 + T2 + T3 + T4 + bval;
        o.y = T1 - T2 + 2.f * T3 - 2.f * T4 + bval;
        o.z = T1 + T2 + 4.f * T3 + 4.f * T4 + bval;
        o.w = T1 - T2 + 8.f * T3 - 8.f * T4 + T5 + bval;
        *(float4*)(yb + (size_t)xr * HH) = o;
    }
}

// ==================== launch ====================
extern "C" void kernel_launch(void* const* d_in, const int* in_sizes, int n_in,
                              void* d_out, int out_size) {
    const float* x    = (const float*)d_in[0];
    const float* wgt  = (const float*)d_in[1];
    const float* bias = (const float*)d_in[2];
    float* y = (float*)d_out;

    const int smemA = (1584 + 36 * 32 * 17) * 4;   // 84672
    cudaFuncSetAttribute(winoA, cudaFuncAttributeMaxDynamicSharedMemorySize, smemA);
    cudaFuncSetAttribute(winoB, cudaFuncAttributeMaxDynamicSharedMemorySize, B_SMEM);

    winoW<<<36, 256>>>(wgt);
    winoA<<<dim3(32, 16), 256, smemA>>>(x);
    winoB<<<dim3(128, 36), 256, B_SMEM>>>();
    winoC<<<4096, 256>>>(bias, y);
}

// round 11
// speedup vs baseline: 2.1799x; 1.0149x over previous
#include <cuda_runtime.h>
#include <cuda_bf16.h>
#include <cstdint>

// ============================================================
// Winograd F(4x4,3x3), filter in 6x6 transform domain.
// 4-kernel pipeline (mma.sync bf16 hi/lo):
//  W: weight split -> Wsc bf16 hi/lo
//  A: input transform -> Vsc bf16 hi/lo  ([p][tile][k], k<64 hi, 64..127 lo)
//     grid (32 tp, 16 n, 4 cin-groups), 16 cins per CTA
//  B: per (point p, 128-tile block): Msc[128][64] =
//     hiV*hiW + loV*hiW + hiV*loW  via mma.sync m16n8k16 bf16
//  C: output transform (AT M A) + bias -> y
// ============================================================

#define HH 128

// ---- scratch ----
__device__ unsigned short Vsc[(size_t)36 * 16384 * 128];  // bf16 bits
__device__ unsigned short Wsc[(size_t)36 * 64 * 128];     // bf16 bits: [p][cout][k]
__device__ float          Msc[(size_t)36 * 16384 * 64];   // [p][tile][cout]

__device__ __forceinline__ uint32_t smem_u32(const void* p) {
    uint32_t a;
    asm("{ .reg .u64 t; cvta.to.shared.u64 t, %1; cvt.u32.u64 %0, t; }" : "=r"(a) : "l"(p));
    return a;
}
__device__ __forceinline__ void ldsm_x4(uint32_t* r, uint32_t addr) {
    asm volatile("ldmatrix.sync.aligned.m8n8.x4.shared.b16 {%0,%1,%2,%3}, [%4];"
        : "=r"(r[0]), "=r"(r[1]), "=r"(r[2]), "=r"(r[3]) : "r"(addr));
}
__device__ __forceinline__ void mma16816(float* c, const uint32_t* a, const uint32_t* b) {
    asm volatile(
        "mma.sync.aligned.m16n8k16.row.col.f32.bf16.bf16.f32 "
        "{%0,%1,%2,%3}, {%4,%5,%6,%7}, {%8,%9}, {%0,%1,%2,%3};\n"
        : "+f"(c[0]), "+f"(c[1]), "+f"(c[2]), "+f"(c[3])
        : "r"(a[0]), "r"(a[1]), "r"(a[2]), "r"(a[3]), "r"(b[0]), "r"(b[1]));
}

// ==================== Kernel W: weight hi/lo split ====================
__global__ __launch_bounds__(256)
void winoW(const float* __restrict__ w)
{
    int p = blockIdx.x;
    int tid = threadIdx.x;
#pragma unroll
    for (int i = 0; i < 16; ++i) {
        int e = tid + (i << 8);
        int co  = e >> 6;
        int cin = e & 63;
        float f = __ldg(w + ((size_t)co * 64 + cin) * 36 + p);
        __nv_bfloat16 h = __float2bfloat16(f);
        __nv_bfloat16 l = __float2bfloat16(f - __bfloat162float(h));
        size_t base = ((size_t)p * 64 + co) * 128;
        Wsc[base + cin]      = __bfloat16_as_ushort(h);
        Wsc[base + 64 + cin] = __bfloat16_as_ushort(l);
    }
}

// ==================== Kernel A: input transform + split ====================
// grid (32 tp, 16 n, 4 cg), 256 threads; each CTA does 16 cins of one strip.
__global__ __launch_bounds__(256, 2)
void winoA(const float* __restrict__ x)
{
    extern __shared__ char smem_raw[];
    float* sm_f = (float*)smem_raw;
    float* sD   = sm_f;            // 792
    float* sU   = sm_f + 792;      // 792
    float* sbuf = sm_f + 1584;     // 36*32*17 = 19584

    const int tid = threadIdx.x;
    const int tp  = blockIdx.x;
    const int n   = blockIdx.y;
    const int cg  = blockIdx.z;    // cin group: cins cg*16 .. cg*16+15
    const int r0  = tp * 4 - 1;

    int dG[4], dI[4]; bool dS[4], dL[4];
#pragma unroll
    for (int k = 0; k < 4; k++) {
        int l = tid + 256 * k;
        bool vl = (l < 780);
        int li = vl ? l : 0;
        int i = li / 130, j = li - i * 130;
        int r = r0 + i, c = j - 1;
        dS[k] = vl;
        dL[k] = vl && ((unsigned)r < HH) && ((unsigned)c < HH);
        dG[k] = r * HH + c;
        dI[k] = i * 132 + j;
    }

    const float* xp = x + ((size_t)n * 64 + cg * 16) * HH * HH;

    for (int cl = 0; cl < 16; ++cl, xp += HH * HH) {
#pragma unroll
        for (int k = 0; k < 4; k++)
            if (dS[k]) sD[dI[k]] = dL[k] ? __ldg(xp + dG[k]) : 0.f;
        __syncthreads();

        if (tid < 130) {
            float d0 = sD[tid], d1 = sD[132 + tid], d2 = sD[264 + tid];
            float d3 = sD[396 + tid], d4 = sD[528 + tid], d5 = sD[660 + tid];
            sU[tid]       =  4.f * d0 - 5.f * d2 + d4;
            sU[132 + tid] = -4.f * d1 - 4.f * d2 + d3 + d4;
            sU[264 + tid] =  4.f * d1 - 4.f * d2 - d3 + d4;
            sU[396 + tid] = -2.f * d1 -       d2 + 2.f * d3 + d4;
            sU[528 + tid] =  2.f * d1 -       d2 - 2.f * d3 + d4;
            sU[660 + tid] =  4.f * d1 - 5.f * d3 + d5;
        }
        __syncthreads();

        if (tid < 192) {
            int a  = tid >> 5;
            int tt = tid & 31;
            const float* u = sU + a * 132 + 4 * tt;
            float u0 = u[0], u1 = u[1], u2 = u[2], u3 = u[3], u4 = u[4], u5 = u[5];
            float* vb = sbuf + ((a * 6) * 32 + tt) * 17 + cl;
            vb[0 * 32 * 17] =  4.f * u0 - 5.f * u2 + u4;
            vb[1 * 32 * 17] = -4.f * u1 - 4.f * u2 + u3 + u4;
            vb[2 * 32 * 17] =  4.f * u1 - 4.f * u2 - u3 + u4;
            vb[3 * 32 * 17] = -2.f * u1 -       u2 + 2.f * u3 + u4;
            vb[4 * 32 * 17] =  2.f * u1 -       u2 - 2.f * u3 + u4;
            vb[5 * 32 * 17] =  4.f * u1 - 5.f * u3 + u5;
        }
        __syncthreads();
    }

    // ---- pack: 16 staged cins -> Vsc hi/lo (streaming stores) ----
    {
        const int cinBase = cg * 16;
        const int c2 = tid & 7;
        const int t  = tid >> 3;
        const int tileg = (n << 10) + (tp << 5) + t;
#pragma unroll 4
        for (int it = 0; it < 36; ++it) {
            float v0 = sbuf[(it * 32 + t) * 17 + 2 * c2];
            float v1 = sbuf[(it * 32 + t) * 17 + 2 * c2 + 1];
            __nv_bfloat16 h0 = __float2bfloat16(v0);
            __nv_bfloat16 h1 = __float2bfloat16(v1);
            __nv_bfloat16 l0 = __float2bfloat16(v0 - __bfloat162float(h0));
            __nv_bfloat16 l1 = __float2bfloat16(v1 - __bfloat162float(h1));
            unsigned hp = (unsigned)__bfloat16_as_ushort(h0) | ((unsigned)__bfloat16_as_ushort(h1) << 16);
            unsigned lp = (unsigned)__bfloat16_as_ushort(l0) | ((unsigned)__bfloat16_as_ushort(l1) << 16);
            size_t base = ((size_t)it * 16384 + tileg) * 128;
            __stcs((unsigned*)&Vsc[base + cinBase + 2 * c2],      hp);
            __stcs((unsigned*)&Vsc[base + 64 + cinBase + 2 * c2], lp);
        }
    }
}

// ==================== Kernel B: mma.sync GEMMs ====================
// grid (128 tile-blocks, 36 points), 256 threads (8 warps: 4 m x 2 n).
#define SMB_A 0
#define SMB_B 32768
#define B_SMEM 49152

__global__ __launch_bounds__(256)
void winoB()
{
    extern __shared__ char smem_raw[];
    uint32_t sbase = smem_u32(smem_raw);
    const int tid  = threadIdx.x;
    const int lane = tid & 31;
    const int wid  = tid >> 5;
    const int tb   = blockIdx.x;
    const int p    = blockIdx.y;

    // ---- stage A: 128 rows x 16 chunks (16B), chunk swizzle c^(row&7) ----
    {
        const uint4* src = (const uint4*)(Vsc + ((size_t)p * 16384 + (size_t)tb * 128) * 128);
        uint4* dst = (uint4*)(smem_raw + SMB_A);
#pragma unroll
        for (int i = 0; i < 8; ++i) {
            int e = tid + (i << 8);
            int row = e >> 4;
            int c   = e & 15;
            dst[row * 16 + (c ^ (row & 7))] = __ldcs(src + row * 16 + c);
        }
    }
    // ---- stage B: 64 rows x 16 chunks ----
    {
        const uint4* src = (const uint4*)(Wsc + (size_t)p * 64 * 128);
        uint4* dst = (uint4*)(smem_raw + SMB_B);
#pragma unroll
        for (int i = 0; i < 4; ++i) {
            int e = tid + (i << 8);
            int row = e >> 4;
            int c   = e & 15;
            dst[row * 16 + (c ^ (row & 7))] = __ldg(src + row * 16 + c);
        }
    }
    __syncthreads();

    const int wm = (wid & 3) * 32;
    const int wn = (wid >> 2) * 32;

    float acc[2][4][4];
#pragma unroll
    for (int a = 0; a < 2; a++)
#pragma unroll
        for (int b = 0; b < 4; b++)
#pragma unroll
            for (int c = 0; c < 4; c++) acc[a][b][c] = 0.f;

    const int arow0 = wm + (lane & 15);
    const int achk  = lane >> 4;
    const int brow0 = wn + (lane & 7) + ((lane >> 4) << 3);
    const int bchk  = (lane >> 3) & 1;

#pragma unroll
    for (int s = 0; s < 12; ++s) {
        const int term = s >> 2, sk = s & 3;
        const int cbA = (term == 1 ? 8 : 0) + 2 * sk;
        const int cbB = (term == 2 ? 8 : 0) + 2 * sk;

        uint32_t aF[2][4];
#pragma unroll
        for (int mt = 0; mt < 2; ++mt) {
            int row = arow0 + mt * 16;
            int chk = (cbA + achk) ^ (row & 7);
            ldsm_x4(aF[mt], sbase + SMB_A + row * 256 + (chk << 4));
        }
        uint32_t bF[2][4];
#pragma unroll
        for (int nt2 = 0; nt2 < 2; ++nt2) {
            int row = brow0 + nt2 * 16;
            int chk = (cbB + bchk) ^ (row & 7);
            ldsm_x4(bF[nt2], sbase + SMB_B + row * 256 + (chk << 4));
        }
#pragma unroll
        for (int mt = 0; mt < 2; ++mt)
#pragma unroll
            for (int nt2 = 0; nt2 < 2; ++nt2) {
                mma16816(acc[mt][nt2 * 2 + 0], aF[mt], &bF[nt2][0]);
                mma16816(acc[mt][nt2 * 2 + 1], aF[mt], &bF[nt2][2]);
            }
    }

    // ---- epilogue: write Msc[p][tile][cout] (streaming) ----
    {
        const int r0 = tb * 128 + wm + (lane >> 2);
        const int c0 = wn + (lane & 3) * 2;
#pragma unroll
        for (int mt = 0; mt < 2; ++mt) {
#pragma unroll
            for (int nt = 0; nt < 4; ++nt) {
                float* d0 = Msc + ((size_t)p * 16384 + r0 + mt * 16) * 64 + c0 + nt * 8;
                __stcs((float2*)d0,            make_float2(acc[mt][nt][0], acc[mt][nt][1]));
                __stcs((float2*)(d0 + 8 * 64), make_float2(acc[mt][nt][2], acc[mt][nt][3]));
            }
        }
    }
}

// ==================== Kernel C: output transform + bias ====================
__global__ __launch_bounds__(256)
void winoC(const float* __restrict__ bias, float* __restrict__ y)
{
    int g = blockIdx.x * 256 + threadIdx.x;
    int cout = g & 63;
    int tile = g >> 6;
    int n  = tile >> 10;
    int ti = (tile >> 5) & 31;
    int tj = tile & 31;

    float m[36];
#pragma unroll
    for (int pp = 0; pp < 36; ++pp)
        m[pp] = __ldcs(Msc + ((size_t)pp * 16384 + tile) * 64 + cout);

    float z[24];
#pragma unroll
    for (int b = 0; b < 6; b++) {
        float m0 = m[b], m1 = m[6 + b], m2 = m[12 + b];
        float m3 = m[18 + b], m4 = m[24 + b], m5 = m[30 + b];
        z[0 * 6 + b] = m0 + m1 + m2 + m3 + m4;
        z[1 * 6 + b] = m1 - m2 + 2.f * m3 - 2.f * m4;
        z[2 * 6 + b] = m1 + m2 + 4.f * m3 + 4.f * m4;
        z[3 * 6 + b] = m1 - m2 + 8.f * m3 - 8.f * m4 + m5;
    }

    float bval = __ldg(bias + cout);
    float* yb = y + (((size_t)(n * 64 + cout)) * HH + ti * 4) * HH + tj * 4;
#pragma unroll
    for (int xr = 0; xr < 4; xr++) {
        float T0 = z[xr * 6 + 0], T1 = z[xr * 6 + 1], T2 = z[xr * 6 + 2];
        float T3 = z[xr * 6 + 3], T4 = z[xr * 6 + 4], T5 = z[xr * 6 + 5];
        float4 o;
        o.x = T0 + T1 + T2 + T3 + T4 + bval;
        o.y = T1 - T2 + 2.f * T3 - 2.f * T4 + bval;
        o.z = T1 + T2 + 4.f * T3 + 4.f * T4 + bval;
        o.w = T1 - T2 + 8.f * T3 - 8.f * T4 + T5 + bval;
        *(float4*)(yb + (size_t)xr * HH) = o;
    }
}

// ==================== launch ====================
extern "C" void kernel_launch(void* const* d_in, const int* in_sizes, int n_in,
                              void* d_out, int out_size) {
    const float* x    = (const float*)d_in[0];
    const float* wgt  = (const float*)d_in[1];
    const float* bias = (const float*)d_in[2];
    float* y = (float*)d_out;

    const int smemA = (1584 + 36 * 32 * 17) * 4;   // 84672
    cudaFuncSetAttribute(winoA, cudaFuncAttributeMaxDynamicSharedMemorySize, smemA);
    cudaFuncSetAttribute(winoB, cudaFuncAttributeMaxDynamicSharedMemorySize, B_SMEM);

    winoW<<<36, 256>>>(wgt);
    winoA<<<dim3(32, 16, 4), 256, smemA>>>(x);
    winoB<<<dim3(128, 36), 256, B_SMEM>>>();
    winoC<<<4096, 256>>>(bias, y);
}

// round 12
// speedup vs baseline: 2.5664x; 1.1773x over previous
#include <cuda_runtime.h>
#include <cuda_bf16.h>
#include <cstdint>

// ============================================================
// Winograd F(4x4,3x3), filter in 6x6 transform domain.
//  W: weight split -> Wsc bf16 hi/lo
//  A: input transform -> Vsc bf16 hi/lo, prefetch-pipelined
//  B: per (point p, 256-tile block): Msc = hiV*hiW + loV*hiW + hiV*loW
//     via mma.sync m16n8k16, warp tile 64x64 (1 wavefront per mma)
//  C: output transform (AT M A) + bias -> y
// ============================================================

#define HH 128

__device__ unsigned short Vsc[(size_t)36 * 16384 * 128];  // [p][tile][k] k<64 hi
__device__ unsigned short Wsc[(size_t)36 * 64 * 128];     // [p][cout][k]
__device__ float          Msc[(size_t)36 * 16384 * 64];   // [p][tile][cout]

__device__ __forceinline__ uint32_t smem_u32(const void* p) {
    uint32_t a;
    asm("{ .reg .u64 t; cvta.to.shared.u64 t, %1; cvt.u32.u64 %0, t; }" : "=r"(a) : "l"(p));
    return a;
}
__device__ __forceinline__ void ldsm_x4(uint32_t* r, uint32_t addr) {
    asm volatile("ldmatrix.sync.aligned.m8n8.x4.shared.b16 {%0,%1,%2,%3}, [%4];"
        : "=r"(r[0]), "=r"(r[1]), "=r"(r[2]), "=r"(r[3]) : "r"(addr));
}
__device__ __forceinline__ void mma16816(float* c, const uint32_t* a, const uint32_t* b) {
    asm volatile(
        "mma.sync.aligned.m16n8k16.row.col.f32.bf16.bf16.f32 "
        "{%0,%1,%2,%3}, {%4,%5,%6,%7}, {%8,%9}, {%0,%1,%2,%3};\n"
        : "+f"(c[0]), "+f"(c[1]), "+f"(c[2]), "+f"(c[3])
        : "r"(a[0]), "r"(a[1]), "r"(a[2]), "r"(a[3]), "r"(b[0]), "r"(b[1]));
}

// ==================== Kernel W ====================
__global__ __launch_bounds__(256)
void winoW(const float* __restrict__ w)
{
    int p = blockIdx.x;
    int tid = threadIdx.x;
#pragma unroll
    for (int i = 0; i < 16; ++i) {
        int e = tid + (i << 8);
        int co  = e >> 6;
        int cin = e & 63;
        float f = __ldg(w + ((size_t)co * 64 + cin) * 36 + p);
        __nv_bfloat16 h = __float2bfloat16(f);
        __nv_bfloat16 l = __float2bfloat16(f - __bfloat162float(h));
        size_t base = ((size_t)p * 64 + co) * 128;
        Wsc[base + cin]      = __bfloat16_as_ushort(h);
        Wsc[base + 64 + cin] = __bfloat16_as_ushort(l);
    }
}

// ==================== Kernel A: input transform (prefetch pipelined) ====
// grid (32 tp, 16 n, 4 cg), 256 threads
__global__ __launch_bounds__(256, 2)
void winoA(const float* __restrict__ x)
{
    extern __shared__ char smem_raw[];
    float* sm_f = (float*)smem_raw;
    float* sD   = sm_f;            // 792
    float* sU   = sm_f + 792;      // 792
    float* sbuf = sm_f + 1584;     // 36*32*17

    const int tid = threadIdx.x;
    const int tp  = blockIdx.x;
    const int n   = blockIdx.y;
    const int cg  = blockIdx.z;
    const int r0  = tp * 4 - 1;

    int dG[4], dI[4]; bool dS[4], dL[4];
#pragma unroll
    for (int k = 0; k < 4; k++) {
        int l = tid + 256 * k;
        bool vl = (l < 780);
        int li = vl ? l : 0;
        int i = li / 130, j = li - i * 130;
        int r = r0 + i, c = j - 1;
        dS[k] = vl;
        dL[k] = vl && ((unsigned)r < HH) && ((unsigned)c < HH);
        dG[k] = r * HH + c;
        dI[k] = i * 132 + j;
    }

    const float* xp = x + ((size_t)n * 64 + cg * 16) * HH * HH;

    // prefetch cl = 0
    float dreg[4];
#pragma unroll
    for (int k = 0; k < 4; k++) dreg[k] = dL[k] ? __ldg(xp + dG[k]) : 0.f;

    for (int cl = 0; cl < 16; ++cl) {
        // commit staged regs
#pragma unroll
        for (int k = 0; k < 4; k++) if (dS[k]) sD[dI[k]] = dreg[k];

        // prefetch next cin (latency hides under U/V transform)
        xp += HH * HH;
        if (cl + 1 < 16) {
#pragma unroll
            for (int k = 0; k < 4; k++) dreg[k] = dL[k] ? __ldg(xp + dG[k]) : 0.f;
        }
        __syncthreads();

        if (tid < 130) {
            float d0 = sD[tid], d1 = sD[132 + tid], d2 = sD[264 + tid];
            float d3 = sD[396 + tid], d4 = sD[528 + tid], d5 = sD[660 + tid];
            sU[tid]       =  4.f * d0 - 5.f * d2 + d4;
            sU[132 + tid] = -4.f * d1 - 4.f * d2 + d3 + d4;
            sU[264 + tid] =  4.f * d1 - 4.f * d2 - d3 + d4;
            sU[396 + tid] = -2.f * d1 -       d2 + 2.f * d3 + d4;
            sU[528 + tid] =  2.f * d1 -       d2 - 2.f * d3 + d4;
            sU[660 + tid] =  4.f * d1 - 5.f * d3 + d5;
        }
        __syncthreads();

        if (tid < 192) {
            int a  = tid >> 5;
            int tt = tid & 31;
            const float* u = sU + a * 132 + 4 * tt;
            float u0 = u[0], u1 = u[1], u2 = u[2], u3 = u[3], u4 = u[4], u5 = u[5];
            float* vb = sbuf + ((a * 6) * 32 + tt) * 17 + cl;
            vb[0 * 32 * 17] =  4.f * u0 - 5.f * u2 + u4;
            vb[1 * 32 * 17] = -4.f * u1 - 4.f * u2 + u3 + u4;
            vb[2 * 32 * 17] =  4.f * u1 - 4.f * u2 - u3 + u4;
            vb[3 * 32 * 17] = -2.f * u1 -       u2 + 2.f * u3 + u4;
            vb[4 * 32 * 17] =  2.f * u1 -       u2 - 2.f * u3 + u4;
            vb[5 * 32 * 17] =  4.f * u1 - 5.f * u3 + u5;
        }
        __syncthreads();
    }

    // ---- pack: 16 staged cins -> Vsc hi/lo ----
    {
        const int cinBase = cg * 16;
        const int c2 = tid & 7;
        const int t  = tid >> 3;
        const int tileg = (n << 10) + (tp << 5) + t;
#pragma unroll 4
        for (int it = 0; it < 36; ++it) {
            float v0 = sbuf[(it * 32 + t) * 17 + 2 * c2];
            float v1 = sbuf[(it * 32 + t) * 17 + 2 * c2 + 1];
            __nv_bfloat16 h0 = __float2bfloat16(v0);
            __nv_bfloat16 h1 = __float2bfloat16(v1);
            __nv_bfloat16 l0 = __float2bfloat16(v0 - __bfloat162float(h0));
            __nv_bfloat16 l1 = __float2bfloat16(v1 - __bfloat162float(h1));
            unsigned hp = (unsigned)__bfloat16_as_ushort(h0) | ((unsigned)__bfloat16_as_ushort(h1) << 16);
            unsigned lp = (unsigned)__bfloat16_as_ushort(l0) | ((unsigned)__bfloat16_as_ushort(l1) << 16);
            size_t base = ((size_t)it * 16384 + tileg) * 128;
            __stcs((unsigned*)&Vsc[base + cinBase + 2 * c2],      hp);
            __stcs((unsigned*)&Vsc[base + 64 + cinBase + 2 * c2], lp);
        }
    }
}

// ==================== Kernel B: mma.sync, warp tile 64x64 ====================
// grid (64 tile-blocks of 256 tiles, 36 points), 128 threads (4 warps).
#define SMB_A 0
#define SMB_B 65536
#define B_SMEM 81920

__global__ __launch_bounds__(128)
void winoB()
{
    extern __shared__ char smem_raw[];
    uint32_t sbase = smem_u32(smem_raw);
    const int tid  = threadIdx.x;
    const int lane = tid & 31;
    const int wid  = tid >> 5;
    const int tb   = blockIdx.x;
    const int p    = blockIdx.y;

    // ---- stage A: 256 rows x 16 chunks (16B), chunk swizzle c^(row&7) ----
    {
        const uint4* src = (const uint4*)(Vsc + ((size_t)p * 16384 + (size_t)tb * 256) * 128);
        uint4* dst = (uint4*)(smem_raw + SMB_A);
#pragma unroll
        for (int i = 0; i < 32; ++i) {
            int e = tid + (i << 7);
            int row = e >> 4;
            int c   = e & 15;
            dst[row * 16 + (c ^ (row & 7))] = __ldcs(src + row * 16 + c);
        }
    }
    // ---- stage B: 64 rows x 16 chunks ----
    {
        const uint4* src = (const uint4*)(Wsc + (size_t)p * 64 * 128);
        uint4* dst = (uint4*)(smem_raw + SMB_B);
#pragma unroll
        for (int i = 0; i < 8; ++i) {
            int e = tid + (i << 7);
            int row = e >> 4;
            int c   = e & 15;
            dst[row * 16 + (c ^ (row & 7))] = __ldg(src + row * 16 + c);
        }
    }
    __syncthreads();

    const int wbase = wid * 64;   // warp covers tiles wbase..wbase+63, all 64 couts

    float acc[4][8][4];
#pragma unroll
    for (int a = 0; a < 4; a++)
#pragma unroll
        for (int b = 0; b < 8; b++)
#pragma unroll
            for (int c = 0; c < 4; c++) acc[a][b][c] = 0.f;

    const int arow = lane & 15;
    const int achk = lane >> 4;
    const int brow0 = (lane & 7) + ((lane >> 4) << 3);
    const int bchk  = (lane >> 3) & 1;

#pragma unroll
    for (int s = 0; s < 12; ++s) {
        const int term = s >> 2, sk = s & 3;
        const int cbA = (term == 1 ? 8 : 0) + 2 * sk;
        const int cbB = (term == 2 ? 8 : 0) + 2 * sk;

        uint32_t bF[4][4];
#pragma unroll
        for (int ng = 0; ng < 4; ++ng) {
            int row = ng * 16 + brow0;
            int chk = (cbB + bchk) ^ (row & 7);
            ldsm_x4(bF[ng], sbase + SMB_B + row * 256 + (chk << 4));
        }
#pragma unroll
        for (int mt = 0; mt < 4; ++mt) {
            uint32_t aF[4];
            int row = wbase + mt * 16 + arow;
            int chk = (cbA + achk) ^ (row & 7);
            ldsm_x4(aF, sbase + SMB_A + row * 256 + (chk << 4));
#pragma unroll
            for (int ng = 0; ng < 4; ++ng) {
                mma16816(acc[mt][ng * 2 + 0], aF, &bF[ng][0]);
                mma16816(acc[mt][ng * 2 + 1], aF, &bF[ng][2]);
            }
        }
    }

    // ---- epilogue: write Msc[p][tile][cout] (streaming) ----
    {
        const int r0 = tb * 256 + wbase + (lane >> 2);
        const int c0 = (lane & 3) * 2;
#pragma unroll
        for (int mt = 0; mt < 4; ++mt) {
#pragma unroll
            for (int j = 0; j < 8; ++j) {
                float* d0 = Msc + ((size_t)p * 16384 + r0 + mt * 16) * 64 + c0 + j * 8;
                __stcs((float2*)d0,            make_float2(acc[mt][j][0], acc[mt][j][1]));
                __stcs((float2*)(d0 + 8 * 64), make_float2(acc[mt][j][2], acc[mt][j][3]));
            }
        }
    }
}

// ==================== Kernel C: output transform + bias ====================
__global__ __launch_bounds__(256)
void winoC(const float* __restrict__ bias, float* __restrict__ y)
{
    int g = blockIdx.x * 256 + threadIdx.x;
    int cout = g & 63;
    int tile = g >> 6;
    int n  = tile >> 10;
    int ti = (tile >> 5) & 31;
    int tj = tile & 31;

    float m[36];
#pragma unroll
    for (int pp = 0; pp < 36; ++pp)
        m[pp] = __ldcs(Msc + ((size_t)pp * 16384 + tile) * 64 + cout);

    float z[24];
#pragma unroll
    for (int b = 0; b < 6; b++) {
        float m0 = m[b], m1 = m[6 + b], m2 = m[12 + b];
        float m3 = m[18 + b], m4 = m[24 + b], m5 = m[30 + b];
        z[0 * 6 + b] = m0 + m1 + m2 + m3 + m4;
        z[1 * 6 + b] = m1 - m2 + 2.f * m3 - 2.f * m4;
        z[2 * 6 + b] = m1 + m2 + 4.f * m3 + 4.f * m4;
        z[3 * 6 + b] = m1 - m2 + 8.f * m3 - 8.f * m4 + m5;
    }

    float bval = __ldg(bias + cout);
    float* yb = y + (((size_t)(n * 64 + cout)) * HH + ti * 4) * HH + tj * 4;
#pragma unroll
    for (int xr = 0; xr < 4; xr++) {
        float T0 = z[xr * 6 + 0], T1 = z[xr * 6 + 1], T2 = z[xr * 6 + 2];
        float T3 = z[xr * 6 + 3], T4 = z[xr * 6 + 4], T5 = z[xr * 6 + 5];
        float4 o;
        o.x = T0 + T1 + T2 + T3 + T4 + bval;
        o.y = T1 - T2 + 2.f * T3 - 2.f * T4 + bval;
        o.z = T1 + T2 + 4.f * T3 + 4.f * T4 + bval;
        o.w = T1 - T2 + 8.f * T3 - 8.f * T4 + T5 + bval;
        *(float4*)(yb + (size_t)xr * HH) = o;
    }
}

// ==================== launch ====================
extern "C" void kernel_launch(void* const* d_in, const int* in_sizes, int n_in,
                              void* d_out, int out_size) {
    const float* x    = (const float*)d_in[0];
    const float* wgt  = (const float*)d_in[1];
    const float* bias = (const float*)d_in[2];
    float* y = (float*)d_out;

    const int smemA = (1584 + 36 * 32 * 17) * 4;   // 84672
    cudaFuncSetAttribute(winoA, cudaFuncAttributeMaxDynamicSharedMemorySize, smemA);
    cudaFuncSetAttribute(winoB, cudaFuncAttributeMaxDynamicSharedMemorySize, B_SMEM);

    winoW<<<36, 256>>>(wgt);
    winoA<<<dim3(32, 16, 4), 256, smemA>>>(x);
    winoB<<<dim3(64, 36), 128, B_SMEM>>>();
    winoC<<<4096, 256>>>(bias, y);
}

// round 13
// speedup vs baseline: 2.8576x; 1.1135x over previous
#include <cuda_runtime.h>
#include <cuda_bf16.h>
#include <cstdint>

// ============================================================
// Winograd F(4x4,3x3), filter in 6x6 transform domain.
//  W: weight split -> Wsc bf16 hi/lo
//  A: input transform -> Vsc bf16 hi/lo; 512 thr, 2 cins per iteration
//  B: per (point p, 256-tile block): Msc = hiV*hiW + loV*hiW + hiV*loW
//     via mma.sync m16n8k16, warp tile 64x64
//  C: output transform (AT M A) + bias -> y
// ============================================================

#define HH 128

__device__ unsigned short Vsc[(size_t)36 * 16384 * 128];  // [p][tile][k] k<64 hi
__device__ unsigned short Wsc[(size_t)36 * 64 * 128];     // [p][cout][k]
__device__ float          Msc[(size_t)36 * 16384 * 64];   // [p][tile][cout]

__device__ __forceinline__ uint32_t smem_u32(const void* p) {
    uint32_t a;
    asm("{ .reg .u64 t; cvta.to.shared.u64 t, %1; cvt.u32.u64 %0, t; }" : "=r"(a) : "l"(p));
    return a;
}
__device__ __forceinline__ void ldsm_x4(uint32_t* r, uint32_t addr) {
    asm volatile("ldmatrix.sync.aligned.m8n8.x4.shared.b16 {%0,%1,%2,%3}, [%4];"
        : "=r"(r[0]), "=r"(r[1]), "=r"(r[2]), "=r"(r[3]) : "r"(addr));
}
__device__ __forceinline__ void mma16816(float* c, const uint32_t* a, const uint32_t* b) {
    asm volatile(
        "mma.sync.aligned.m16n8k16.row.col.f32.bf16.bf16.f32 "
        "{%0,%1,%2,%3}, {%4,%5,%6,%7}, {%8,%9}, {%0,%1,%2,%3};\n"
        : "+f"(c[0]), "+f"(c[1]), "+f"(c[2]), "+f"(c[3])
        : "r"(a[0]), "r"(a[1]), "r"(a[2]), "r"(a[3]), "r"(b[0]), "r"(b[1]));
}

// ==================== Kernel W ====================
__global__ __launch_bounds__(256)
void winoW(const float* __restrict__ w)
{
    int p = blockIdx.x;
    int tid = threadIdx.x;
#pragma unroll
    for (int i = 0; i < 16; ++i) {
        int e = tid + (i << 8);
        int co  = e >> 6;
        int cin = e & 63;
        float f = __ldg(w + ((size_t)co * 64 + cin) * 36 + p);
        __nv_bfloat16 h = __float2bfloat16(f);
        __nv_bfloat16 l = __float2bfloat16(f - __bfloat162float(h));
        size_t base = ((size_t)p * 64 + co) * 128;
        Wsc[base + cin]      = __bfloat16_as_ushort(h);
        Wsc[base + 64 + cin] = __bfloat16_as_ushort(l);
    }
}

// ==================== Kernel A: 512 threads, 2 cins/iter ====================
// grid (32 tp, 16 n, 4 cg); 16 cins per CTA in 8 iterations.
__global__ __launch_bounds__(512, 2)
void winoA(const float* __restrict__ x)
{
    extern __shared__ char smem_raw[];
    float* sm_f = (float*)smem_raw;
    float* sD   = sm_f;            // 2 x 792
    float* sU   = sm_f + 1584;     // 2 x 792
    float* sbuf = sm_f + 3168;     // 36*32*17 = 19584

    const int tid = threadIdx.x;
    const int tp  = blockIdx.x;
    const int n   = blockIdx.y;
    const int cg  = blockIdx.z;
    const int r0  = tp * 4 - 1;

    // staging indices: 1560 elements = 2 cins x (6 x 130)
    int dG[4], dI[4]; bool dS[4], dL[4];
#pragma unroll
    for (int k = 0; k < 4; k++) {
        int l = tid + 512 * k;
        bool vl = (l < 1560);
        int li = vl ? l : 0;
        int ci  = li / 780;
        int rem = li - ci * 780;
        int i = rem / 130, j = rem - i * 130;
        int r = r0 + i, c = j - 1;
        dS[k] = vl;
        dL[k] = vl && ((unsigned)r < HH) && ((unsigned)c < HH);
        dG[k] = ci * (HH * HH) + r * HH + c;
        dI[k] = ci * 792 + i * 132 + j;
    }

    // hoisted phase mappings
    const int uci  = (tid < 260) ? (tid / 130) : 0;
    const int ucol = tid - uci * 130;
    const int vci  = (tid < 384) ? (tid / 192) : 0;
    const int vsub = tid - vci * 192;
    const int va   = vsub >> 5;
    const int vtt  = vsub & 31;

    const float* xcur = x + ((size_t)n * 64 + cg * 16) * HH * HH;

    // prefetch iter 0 (cins 0,1)
    float dreg[4];
#pragma unroll
    for (int k = 0; k < 4; k++) dreg[k] = dL[k] ? __ldg(xcur + dG[k]) : 0.f;

    for (int itc = 0; itc < 8; ++itc) {
        // commit staged regs
#pragma unroll
        for (int k = 0; k < 4; k++) if (dS[k]) sD[dI[k]] = dreg[k];

        // prefetch next pair
        xcur += 2 * HH * HH;
        if (itc + 1 < 8) {
#pragma unroll
            for (int k = 0; k < 4; k++) dreg[k] = dL[k] ? __ldg(xcur + dG[k]) : 0.f;
        }
        __syncthreads();

        // U = BT @ D for both cins (260 threads)
        if (tid < 260) {
            const float* d = sD + uci * 792 + ucol;
            float* u = sU + uci * 792 + ucol;
            float d0 = d[0], d1 = d[132], d2 = d[264];
            float d3 = d[396], d4 = d[528], d5 = d[660];
            u[0]   =  4.f * d0 - 5.f * d2 + d4;
            u[132] = -4.f * d1 - 4.f * d2 + d3 + d4;
            u[264] =  4.f * d1 - 4.f * d2 - d3 + d4;
            u[396] = -2.f * d1 -       d2 + 2.f * d3 + d4;
            u[528] =  2.f * d1 -       d2 - 2.f * d3 + d4;
            u[660] =  4.f * d1 - 5.f * d3 + d5;
        }
        __syncthreads();

        // V for both cins (384 threads)
        if (tid < 384) {
            const float* u = sU + vci * 792 + va * 132 + 4 * vtt;
            float u0 = u[0], u1 = u[1], u2 = u[2], u3 = u[3], u4 = u[4], u5 = u[5];
            int cl = itc * 2 + vci;
            float* vb = sbuf + ((va * 6) * 32 + vtt) * 17 + cl;
            vb[0 * 32 * 17] =  4.f * u0 - 5.f * u2 + u4;
            vb[1 * 32 * 17] = -4.f * u1 - 4.f * u2 + u3 + u4;
            vb[2 * 32 * 17] =  4.f * u1 - 4.f * u2 - u3 + u4;
            vb[3 * 32 * 17] = -2.f * u1 -       u2 + 2.f * u3 + u4;
            vb[4 * 32 * 17] =  2.f * u1 -       u2 - 2.f * u3 + u4;
            vb[5 * 32 * 17] =  4.f * u1 - 5.f * u3 + u5;
        }
        __syncthreads();
    }

    // ---- pack: 16 staged cins -> Vsc hi/lo (2 points per iter) ----
    {
        const int cinBase = cg * 16;
        const int c2 = tid & 7;
        const int t  = (tid >> 3) & 31;
        const int ph = tid >> 8;            // 0/1: which of 2 points
        const int tileg = (n << 10) + (tp << 5) + t;
#pragma unroll 4
        for (int it = 0; it < 18; ++it) {
            int p = it * 2 + ph;
            float v0 = sbuf[(p * 32 + t) * 17 + 2 * c2];
            float v1 = sbuf[(p * 32 + t) * 17 + 2 * c2 + 1];
            __nv_bfloat16 h0 = __float2bfloat16(v0);
            __nv_bfloat16 h1 = __float2bfloat16(v1);
            __nv_bfloat16 l0 = __float2bfloat16(v0 - __bfloat162float(h0));
            __nv_bfloat16 l1 = __float2bfloat16(v1 - __bfloat162float(h1));
            unsigned hp = (unsigned)__bfloat16_as_ushort(h0) | ((unsigned)__bfloat16_as_ushort(h1) << 16);
            unsigned lp = (unsigned)__bfloat16_as_ushort(l0) | ((unsigned)__bfloat16_as_ushort(l1) << 16);
            size_t base = ((size_t)p * 16384 + tileg) * 128;
            __stcs((unsigned*)&Vsc[base + cinBase + 2 * c2],      hp);
            __stcs((unsigned*)&Vsc[base + 64 + cinBase + 2 * c2], lp);
        }
    }
}

// ==================== Kernel B: mma.sync, warp tile 64x64 ====================
// grid (64 tile-blocks of 256 tiles, 36 points), 128 threads (4 warps).
#define SMB_A 0
#define SMB_B 65536
#define B_SMEM 81920

__global__ __launch_bounds__(128)
void winoB()
{
    extern __shared__ char smem_raw[];
    uint32_t sbase = smem_u32(smem_raw);
    const int tid  = threadIdx.x;
    const int lane = tid & 31;
    const int wid  = tid >> 5;
    const int tb   = blockIdx.x;
    const int p    = blockIdx.y;

    // ---- stage A: 256 rows x 16 chunks (16B), chunk swizzle c^(row&7) ----
    {
        const uint4* src = (const uint4*)(Vsc + ((size_t)p * 16384 + (size_t)tb * 256) * 128);
        uint4* dst = (uint4*)(smem_raw + SMB_A);
#pragma unroll
        for (int i = 0; i < 32; ++i) {
            int e = tid + (i << 7);
            int row = e >> 4;
            int c   = e & 15;
            dst[row * 16 + (c ^ (row & 7))] = __ldcs(src + row * 16 + c);
        }
    }
    // ---- stage B: 64 rows x 16 chunks ----
    {
        const uint4* src = (const uint4*)(Wsc + (size_t)p * 64 * 128);
        uint4* dst = (uint4*)(smem_raw + SMB_B);
#pragma unroll
        for (int i = 0; i < 8; ++i) {
            int e = tid + (i << 7);
            int row = e >> 4;
            int c   = e & 15;
            dst[row * 16 + (c ^ (row & 7))] = __ldg(src + row * 16 + c);
        }
    }
    __syncthreads();

    const int wbase = wid * 64;

    float acc[4][8][4];
#pragma unroll
    for (int a = 0; a < 4; a++)
#pragma unroll
        for (int b = 0; b < 8; b++)
#pragma unroll
            for (int c = 0; c < 4; c++) acc[a][b][c] = 0.f;

    const int arow = lane & 15;
    const int achk = lane >> 4;
    const int brow0 = (lane & 7) + ((lane >> 4) << 3);
    const int bchk  = (lane >> 3) & 1;

#pragma unroll
    for (int s = 0; s < 12; ++s) {
        const int term = s >> 2, sk = s & 3;
        const int cbA = (term == 1 ? 8 : 0) + 2 * sk;
        const int cbB = (term == 2 ? 8 : 0) + 2 * sk;

        uint32_t bF[4][4];
#pragma unroll
        for (int ng = 0; ng < 4; ++ng) {
            int row = ng * 16 + brow0;
            int chk = (cbB + bchk) ^ (row & 7);
            ldsm_x4(bF[ng], sbase + SMB_B + row * 256 + (chk << 4));
        }
#pragma unroll
        for (int mt = 0; mt < 4; ++mt) {
            uint32_t aF[4];
            int row = wbase + mt * 16 + arow;
            int chk = (cbA + achk) ^ (row & 7);
            ldsm_x4(aF, sbase + SMB_A + row * 256 + (chk << 4));
#pragma unroll
            for (int ng = 0; ng < 4; ++ng) {
                mma16816(acc[mt][ng * 2 + 0], aF, &bF[ng][0]);
                mma16816(acc[mt][ng * 2 + 1], aF, &bF[ng][2]);
            }
        }
    }

    // ---- epilogue ----
    {
        const int r0 = tb * 256 + wbase + (lane >> 2);
        const int c0 = (lane & 3) * 2;
#pragma unroll
        for (int mt = 0; mt < 4; ++mt) {
#pragma unroll
            for (int j = 0; j < 8; ++j) {
                float* d0 = Msc + ((size_t)p * 16384 + r0 + mt * 16) * 64 + c0 + j * 8;
                __stcs((float2*)d0,            make_float2(acc[mt][j][0], acc[mt][j][1]));
                __stcs((float2*)(d0 + 8 * 64), make_float2(acc[mt][j][2], acc[mt][j][3]));
            }
        }
    }
}

// ==================== Kernel C: output transform + bias ====================
__global__ __launch_bounds__(256)
void winoC(const float* __restrict__ bias, float* __restrict__ y)
{
    int g = blockIdx.x * 256 + threadIdx.x;
    int cout = g & 63;
    int tile = g >> 6;
    int n  = tile >> 10;
    int ti = (tile >> 5) & 31;
    int tj = tile & 31;

    float m[36];
#pragma unroll
    for (int pp = 0; pp < 36; ++pp)
        m[pp] = __ldcs(Msc + ((size_t)pp * 16384 + tile) * 64 + cout);

    float z[24];
#pragma unroll
    for (int b = 0; b < 6; b++) {
        float m0 = m[b], m1 = m[6 + b], m2 = m[12 + b];
        float m3 = m[18 + b], m4 = m[24 + b], m5 = m[30 + b];
        z[0 * 6 + b] = m0 + m1 + m2 + m3 + m4;
        z[1 * 6 + b] = m1 - m2 + 2.f * m3 - 2.f * m4;
        z[2 * 6 + b] = m1 + m2 + 4.f * m3 + 4.f * m4;
        z[3 * 6 + b] = m1 - m2 + 8.f * m3 - 8.f * m4 + m5;
    }

    float bval = __ldg(bias + cout);
    float* yb = y + (((size_t)(n * 64 + cout)) * HH + ti * 4) * HH + tj * 4;
#pragma unroll
    for (int xr = 0; xr < 4; xr++) {
        float T0 = z[xr * 6 + 0], T1 = z[xr * 6 + 1], T2 = z[xr * 6 + 2];
        float T3 = z[xr * 6 + 3], T4 = z[xr * 6 + 4], T5 = z[xr * 6 + 5];
        float4 o;
        o.x = T0 + T1 + T2 + T3 + T4 + bval;
        o.y = T1 - T2 + 2.f * T3 - 2.f * T4 + bval;
        o.z = T1 + T2 + 4.f * T3 + 4.f * T4 + bval;
        o.w = T1 - T2 + 8.f * T3 - 8.f * T4 + T5 + bval;
        *(float4*)(yb + (size_t)xr * HH) = o;
    }
}

// ==================== launch ====================
extern "C" void kernel_launch(void* const* d_in, const int* in_sizes, int n_in,
                              void* d_out, int out_size) {
    const float* x    = (const float*)d_in[0];
    const float* wgt  = (const float*)d_in[1];
    const float* bias = (const float*)d_in[2];
    float* y = (float*)d_out;

    const int smemA = (3168 + 36 * 32 * 17) * 4;   // 91008
    cudaFuncSetAttribute(winoA, cudaFuncAttributeMaxDynamicSharedMemorySize, smemA);
    cudaFuncSetAttribute(winoB, cudaFuncAttributeMaxDynamicSharedMemorySize, B_SMEM);

    winoW<<<36, 256>>>(wgt);
    winoA<<<dim3(32, 16, 4), 512, smemA>>>(x);
    winoB<<<dim3(64, 36), 128, B_SMEM>>>();
    winoC<<<4096, 256>>>(bias, y);
}